// round 17
// baseline (speedup 1.0000x reference)
#include <cuda_runtime.h>
#include <cuda_fp16.h>
#include <stdint.h>
#include <math.h>

#define NMAX 100000

__device__ __align__(16) float g_segsum[(size_t)NMAX * 64];
__device__ float g_cnt[NMAX];
__device__ float g_esum[64];
__device__ float g_nsum[64];
__device__ unsigned g_ctr;
__device__ __align__(16) __half g_xh[(size_t)NMAX * 64];
__device__ __align__(16) __half g_gh[16];

// fp16 hi-only weight fragments uint2 = {b0,b1}, layout [kc][nt8][lane]
__device__ __align__(16) uint2 g_w1f[13 * 16 * 32];
__device__ __align__(16) uint2 g_w2f[8 * 8 * 32];
__device__ __align__(16) uint2 g_wn1f[9 * 16 * 32];
__device__ __align__(16) uint2 g_wn2f[8 * 8 * 32];

// ---------------- helpers ----------------
__device__ __forceinline__ uint32_t smem_u32(const void* p) {
    uint32_t a;
    asm("{ .reg .u64 t; cvta.to.shared.u64 t, %1; cvt.u32.u64 %0, t; }" : "=r"(a) : "l"(p));
    return a;
}
#define LDSM_X4(r, a) asm volatile( \
    "ldmatrix.sync.aligned.m8n8.x4.shared.b16 {%0,%1,%2,%3}, [%4];" \
    : "=r"((r)[0]), "=r"((r)[1]), "=r"((r)[2]), "=r"((r)[3]) : "r"(a))
#define MMA16816(d, a, b0, b1) asm volatile( \
    "mma.sync.aligned.m16n8k16.row.col.f32.f16.f16.f32 " \
    "{%0,%1,%2,%3}, {%4,%5,%6,%7}, {%8,%9}, {%0,%1,%2,%3};" \
    : "+f"((d)[0]), "+f"((d)[1]), "+f"((d)[2]), "+f"((d)[3]) \
    : "r"((a)[0]), "r"((a)[1]), "r"((a)[2]), "r"((a)[3]), "r"(b0), "r"(b1))
#define BARC256(id) asm volatile("bar.sync %0, 256;" :: "r"(id) : "memory")

__device__ __forceinline__ void mbar_init(uint32_t m, uint32_t c) {
    asm volatile("mbarrier.init.shared.b64 [%0], %1;" :: "r"(m), "r"(c) : "memory");
}
__device__ __forceinline__ void mbar_arrive(uint32_t m) {
    asm volatile("mbarrier.arrive.shared.b64 _, [%0];" :: "r"(m) : "memory");
}
__device__ __forceinline__ void mbar_wait(uint32_t m, int ph) {
    asm volatile("{ .reg .pred P;\nLW%=: mbarrier.try_wait.parity.acquire.cta.shared::cta.b64 P, [%0], %1, 0x989680;\n@P bra LD%=;\nbra LW%=;\nLD%=: }"
                 :: "r"(m), "r"(ph) : "memory");
}
__device__ __forceinline__ void redv2(float* p, float a, float b) {
    asm volatile("{ .reg .u64 q; cvta.to.global.u64 q, %0;\n"
                 "red.global.add.v2.f32 [q], {%1,%2}; }"
                 :: "l"(p), "f"(a), "f"(b) : "memory");
}

// ---------------- fused setup: zero + weights + x/g fp16 convert ----------------
__device__ __forceinline__ uint2 mkfrag2(const float* W, int ncols, int kc, int nt8, int lane) {
    int k0 = kc * 16 + 2 * (lane & 3);
    int n  = nt8 * 8 + (lane >> 2);
    __half2 a = __floats2half2_rn(W[(size_t)k0 * ncols + n], W[(size_t)(k0 + 1) * ncols + n]);
    __half2 b = __floats2half2_rn(W[(size_t)(k0 + 8) * ncols + n], W[(size_t)(k0 + 9) * ncols + n]);
    return make_uint2(*(uint32_t*)&a, *(uint32_t*)&b);
}
__device__ __forceinline__ uint2 cvt4h(float4 v) {
    __half2 h0 = __floats2half2_rn(v.x, v.y);
    __half2 h1 = __floats2half2_rn(v.z, v.w);
    return make_uint2(*(uint32_t*)&h0, *(uint32_t*)&h1);
}
__global__ void setup_kernel(int N, const float* x, const float* gf,
                             const float* We1, const float* We2,
                             const float* Wn1, const float* Wn2) {
    size_t gi = (size_t)blockIdx.x * blockDim.x + threadIdx.x;
    if (gi < (size_t)N * 16) {
        ((float4*)g_segsum)[gi] = make_float4(0.f, 0.f, 0.f, 0.f);
        *(uint2*)(g_xh + gi * 4) = cvt4h(((const float4*)x)[gi]);
    }
    if (gi < (size_t)N) g_cnt[gi] = 0.f;
    if (gi < 64) { g_esum[gi] = 0.f; g_nsum[gi] = 0.f; }
    if (gi == 0) g_ctr = 0u;
    if (gi < 4)  *(uint2*)(g_gh + gi * 4) = cvt4h(((const float4*)gf)[gi]);
    int i = (int)gi;
    if (i < 13 * 16 * 32) { int kc = i >> 9, r = i & 511; g_w1f[i] = mkfrag2(We1, 128, kc, r >> 5, r & 31); return; }
    i -= 13 * 16 * 32;
    if (i < 8 * 8 * 32)   { int kc = i >> 8, r = i & 255; g_w2f[i] = mkfrag2(We2, 64, kc, r >> 5, r & 31); return; }
    i -= 8 * 8 * 32;
    if (i < 9 * 16 * 32)  { int kc = i >> 9, r = i & 511; g_wn1f[i] = mkfrag2(Wn1, 128, kc, r >> 5, r & 31); return; }
    i -= 9 * 16 * 32;
    if (i < 8 * 8 * 32)   { int kc = i >> 8, r = i & 255; g_wn2f[i] = mkfrag2(Wn2, 64, kc, r >> 5, r & 31); }
}

// ---------------- consumer MLP: 8 warps (2M x 4N), 64-row tile ----------------
template<int SA2, int KC1>
__device__ __forceinline__ void tile_mlp(char* sm, uint32_t sbase,
    uint32_t offA, uint32_t offH,
    const uint2* __restrict__ W1f, const uint2* __restrict__ W2f,
    const float* b1s, int wm, int wn, int lane, uint32_t emptyAddr,
    float (&d2)[2][2][4])
{
    float d1[2][4][4];
#pragma unroll
    for (int m = 0; m < 2; m++)
#pragma unroll
        for (int j = 0; j < 4; j++)
#pragma unroll
            for (int k = 0; k < 4; k++) d1[m][j][k] = 0.f;

    const uint32_t aA = sbase + offA +
        (uint32_t)(32 * wm * SA2 + (lane & 15) * SA2 + (lane >> 4) * 16);
    const uint2* __restrict__ w1p = W1f + 4 * wn * 32 + lane;

    for (int kc = 0; kc < KC1; kc++) {
        uint32_t ah[2][4];
        LDSM_X4(ah[0], aA + kc * 32);
        LDSM_X4(ah[1], aA + (uint32_t)(16 * SA2) + kc * 32);
        uint2 w[4];
#pragma unroll
        for (int j = 0; j < 4; j++) w[j] = __ldg(w1p + kc * 512 + j * 32);
#pragma unroll
        for (int m = 0; m < 2; m++)
#pragma unroll
            for (int j = 0; j < 4; j++)
                MMA16816(d1[m][j], ah[m], w[j].x, w[j].y);
    }
    mbar_arrive(emptyAddr);   // A slot free for producer

    // epi1: H = relu(D1 + b1) -> fp16, stride 136 halves (272B)
#pragma unroll
    for (int m = 0; m < 2; m++)
#pragma unroll
        for (int j = 0; j < 4; j++) {
            int c = 32 * wn + 8 * j + 2 * (lane & 3);
            int R = 32 * wm + 16 * m + (lane >> 2);
            __half2 p0 = __floats2half2_rn(fmaxf(d1[m][j][0] + b1s[c], 0.f),
                                           fmaxf(d1[m][j][1] + b1s[c + 1], 0.f));
            *(__half2*)(sm + offH + (R * 136 + c) * 2) = p0;
            __half2 p1 = __floats2half2_rn(fmaxf(d1[m][j][2] + b1s[c], 0.f),
                                           fmaxf(d1[m][j][3] + b1s[c + 1], 0.f));
            *(__half2*)(sm + offH + ((R + 8) * 136 + c) * 2) = p1;
        }
    BARC256(1);   // H visible (only barrier per tile)

    // GEMM2: 32 rows x 16 cols per warp, K=128, single term (Hh * W2h)
#pragma unroll
    for (int m = 0; m < 2; m++)
#pragma unroll
        for (int j = 0; j < 2; j++)
#pragma unroll
            for (int k = 0; k < 4; k++) d2[m][j][k] = 0.f;

    const uint32_t aH = sbase + offH +
        (uint32_t)(32 * wm * 272 + (lane & 15) * 272 + (lane >> 4) * 16);
    const uint2* __restrict__ w2p = W2f + 2 * wn * 32 + lane;

#pragma unroll
    for (int kc = 0; kc < 8; kc++) {
        uint32_t hh[2][4];
        LDSM_X4(hh[0], aH + kc * 32);
        LDSM_X4(hh[1], aH + (uint32_t)(16 * 272) + kc * 32);
        uint2 w0 = __ldg(w2p + kc * 256);
        uint2 w1 = __ldg(w2p + kc * 256 + 32);
#pragma unroll
        for (int m = 0; m < 2; m++) {
            MMA16816(d2[m][0], hh[m], w0.x, w0.y);
            MMA16816(d2[m][1], hh[m], w1.x, w1.y);
        }
    }
    // no trailing barrier: H double-buffered
}

// ---------------- edge kernel ----------------
extern __shared__ char dsm[];

#define E_SA2  432
#define E_SLOT 27648u
#define E_HB   82944u
#define E_HSZ  17408u
#define E_SMEM 117760

__global__ __launch_bounds__(512, 1)
void edge_tc(const int* __restrict__ ei, const float* __restrict__ ea,
             const float* __restrict__ b1, const float* __restrict__ b2,
             float* __restrict__ eout, int E, int N, int ntiles)
{
    __shared__ float b1s[128], b2s[64], redbuf[64];
    __shared__ __align__(16) unsigned long long s_bar[6];
    const int tid = threadIdx.x, lane = tid & 31;
    const uint32_t sbase = smem_u32(dsm);
    const uint32_t bAf = smem_u32(&s_bar[0]), bAe = smem_u32(&s_bar[3]);

    if (tid < 128) b1s[tid] = b1[tid];
    if (tid < 64)  { b2s[tid] = b2[tid]; redbuf[tid] = 0.f; }
    if (tid == 0) {
#pragma unroll
        for (int s = 0; s < 3; s++) {
            mbar_init(bAf + 8 * s, 256);
            mbar_init(bAe + 8 * s, 256);
        }
    }
    __syncthreads();

    if (tid < 256) {  // ---- consumers (8 warps: 2M x 4N) ----
        const int wid = tid >> 5, wm = wid >> 2, wn = wid & 3;
        float acc[2][2] = {{0.f, 0.f}, {0.f, 0.f}};
        int s = 0, wrap = 0, it = 0;
        for (int t = blockIdx.x; t < ntiles; t += gridDim.x) {
            mbar_wait(bAf + 8 * s, wrap & 1);
            float d2[2][2][4];
            tile_mlp<E_SA2, 13>(dsm, sbase, s * E_SLOT, E_HB + (uint32_t)(it & 1) * E_HSZ,
                                g_w1f, g_w2f, b1s, wm, wn, lane, bAe + 8 * s, d2);
#pragma unroll
            for (int m = 0; m < 2; m++)
#pragma unroll
                for (int h = 0; h < 2; h++) {
                    int row = 32 * wm + 16 * m + (lane >> 2) + 8 * h;
                    int ge = t * 64 + row;
                    if (ge < E) {
                        int r = ei[ge]; r = min(max(r, 0), N - 1);
#pragma unroll
                        for (int j = 0; j < 2; j++) {
                            int c = 16 * wn + 8 * j + 2 * (lane & 3);
                            float v0 = d2[m][j][2 * h]     + b2s[c];
                            float v1 = d2[m][j][2 * h + 1] + b2s[c + 1];
                            *(float2*)(eout + (size_t)ge * 64 + c) = make_float2(v0, v1);
                            redv2(g_segsum + (size_t)r * 64 + c, v0, v1);
                            acc[j][0] += v0; acc[j][1] += v1;
                        }
                        if (wn == 0 && (lane & 3) == 0) atomicAdd(&g_cnt[r], 1.f);
                    }
                }
            s++; if (s == 3) { s = 0; wrap++; }
            it++;
        }
#pragma unroll
        for (int j = 0; j < 2; j++) {
            atomicAdd(&redbuf[16 * wn + 8 * j + 2 * (lane & 3)], acc[j][0]);
            atomicAdd(&redbuf[16 * wn + 8 * j + 2 * (lane & 3) + 1], acc[j][1]);
        }
        BARC256(2);
        if (tid < 64) atomicAdd(&g_esum[tid], redbuf[tid]);
    } else {  // ---- producers (8 warps, 4 threads/row) ----
        const int pt = tid - 256;
        const int e = pt >> 2, q = pt & 3;
        int s = 0, wrap = 0, it = 0;
        for (int t = blockIdx.x; t < ntiles; t += gridDim.x) {
            if (it >= 3) mbar_wait(bAe + 8 * s, (wrap - 1) & 1);
            int ge = t * 64 + e;
            bool v = ge < E;
            int r = 0, c = 0;
            if (v) {
                r = ei[ge]; c = ei[E + ge];
                r = min(max(r, 0), N - 1); c = min(max(c, 0), N - 1);
            }
            char* sb = dsm + s * E_SLOT;
            const float4* e4 = (const float4*)(ea + (size_t)ge * 64);
            uint2 hv[13];
#pragma unroll
            for (int j = 0; j < 13; j++) {
                int c4 = q + 4 * j;
                uint2 w = make_uint2(0u, 0u);
                if (v) {
                    if (c4 < 4)       w = *(const uint2*)(g_gh + c4 * 4);
                    else if (c4 < 20) w = *(const uint2*)(g_xh + (size_t)r * 64 + (c4 - 4) * 4);
                    else if (c4 < 36) w = *(const uint2*)(g_xh + (size_t)c * 64 + (c4 - 20) * 4);
                    else              w = cvt4h(e4[c4 - 36]);
                }
                hv[j] = w;
            }
#pragma unroll
            for (int j = 0; j < 13; j++)
                *(uint2*)(sb + (uint32_t)(e * E_SA2 + (q + 4 * j) * 8)) = hv[j];
            mbar_arrive(bAf + 8 * s);
            s++; if (s == 3) { s = 0; wrap++; }
            it++;
        }
    }
}

// ---------------- node kernel (+ fused global MLP in last CTA) ----------------
#define N_SA2  304
#define N_SLOT 19456u
#define N_HB   58368u
#define N_HSZ  17408u
#define N_SMEM 93184

__global__ __launch_bounds__(512, 1)
void node_tc(const float* __restrict__ gfp,
             const float* __restrict__ b1, const float* __restrict__ b2,
             float* __restrict__ nout, int N, int ntiles, int E,
             const float* __restrict__ Wg1, const float* __restrict__ bg1,
             const float* __restrict__ Wg2, const float* __restrict__ bg2,
             float* __restrict__ gout)
{
    __shared__ float b1s[128], b2s[64], redbuf[64];
    __shared__ __align__(16) unsigned long long s_bar[6];
    __shared__ int s_last;
    __shared__ float gin[144], ghid[128];
    const int tid = threadIdx.x, lane = tid & 31;
    const uint32_t sbase = smem_u32(dsm);
    const uint32_t bAf = smem_u32(&s_bar[0]), bAe = smem_u32(&s_bar[3]);

    if (tid < 128) b1s[tid] = b1[tid];
    if (tid < 64)  { b2s[tid] = b2[tid]; redbuf[tid] = 0.f; }
    if (tid == 0) {
#pragma unroll
        for (int s = 0; s < 3; s++) {
            mbar_init(bAf + 8 * s, 256);
            mbar_init(bAe + 8 * s, 256);
        }
    }
    __syncthreads();

    if (tid < 256) {  // consumers
        const int wid = tid >> 5, wm = wid >> 2, wn = wid & 3;
        float acc[2][2] = {{0.f, 0.f}, {0.f, 0.f}};
        int s = 0, wrap = 0, it = 0;
        for (int t = blockIdx.x; t < ntiles; t += gridDim.x) {
            mbar_wait(bAf + 8 * s, wrap & 1);
            float d2[2][2][4];
            tile_mlp<N_SA2, 9>(dsm, sbase, s * N_SLOT, N_HB + (uint32_t)(it & 1) * N_HSZ,
                               g_wn1f, g_wn2f, b1s, wm, wn, lane, bAe + 8 * s, d2);
#pragma unroll
            for (int m = 0; m < 2; m++)
#pragma unroll
                for (int h = 0; h < 2; h++) {
                    int row = 32 * wm + 16 * m + (lane >> 2) + 8 * h;
                    int n = t * 64 + row;
                    if (n < N) {
#pragma unroll
                        for (int j = 0; j < 2; j++) {
                            int c = 16 * wn + 8 * j + 2 * (lane & 3);
                            float v0 = d2[m][j][2 * h]     + b2s[c];
                            float v1 = d2[m][j][2 * h + 1] + b2s[c + 1];
                            *(float2*)(nout + (size_t)n * 64 + c) = make_float2(v0, v1);
                            acc[j][0] += v0; acc[j][1] += v1;
                        }
                    }
                }
            s++; if (s == 3) { s = 0; wrap++; }
            it++;
        }
#pragma unroll
        for (int j = 0; j < 2; j++) {
            atomicAdd(&redbuf[16 * wn + 8 * j + 2 * (lane & 3)], acc[j][0]);
            atomicAdd(&redbuf[16 * wn + 8 * j + 2 * (lane & 3) + 1], acc[j][1]);
        }
        BARC256(2);
        if (tid < 64) { atomicAdd(&g_nsum[tid], redbuf[tid]); __threadfence(); }
    } else {  // producers
        const int pt = tid - 256;
        const int e = pt >> 2, q = pt & 3;
        int s = 0, wrap = 0, it = 0;
        for (int t = blockIdx.x; t < ntiles; t += gridDim.x) {
            if (it >= 3) mbar_wait(bAe + 8 * s, (wrap - 1) & 1);
            int n = t * 64 + e;
            bool v = n < N;
            float inv = 1.f;
            if (v) inv = 1.0f / fmaxf(g_cnt[n], 1.0f);
            char* sb = dsm + s * N_SLOT;
            const float4* sg = (const float4*)(g_segsum + (size_t)n * 64);
            uint2 hv[9];
#pragma unroll
            for (int j = 0; j < 9; j++) {
                int c4 = q + 4 * j;
                uint2 w = make_uint2(0u, 0u);
                if (v) {
                    if (c4 < 4)       w = *(const uint2*)(g_gh + c4 * 4);
                    else if (c4 < 20) w = *(const uint2*)(g_xh + (size_t)n * 64 + (c4 - 4) * 4);
                    else {
                        float4 p = sg[c4 - 20];
                        w = cvt4h(make_float4(p.x * inv, p.y * inv, p.z * inv, p.w * inv));
                    }
                }
                hv[j] = w;
            }
#pragma unroll
            for (int j = 0; j < 9; j++)
                *(uint2*)(sb + (uint32_t)(e * N_SA2 + (q + 4 * j) * 8)) = hv[j];
            mbar_arrive(bAf + 8 * s);
            s++; if (s == 3) { s = 0; wrap++; }
            it++;
        }
    }

    // ---- last-CTA: fused global MLP ----
    __syncthreads();
    if (tid == 0) {
        unsigned v = atomicAdd(&g_ctr, 1u);
        s_last = (v == gridDim.x - 1) ? 1 : 0;
    }
    __syncthreads();
    if (s_last) {
        if (tid < 64)       gin[tid] = atomicAdd(&g_nsum[tid], 0.f) / (float)N;
        else if (tid < 128) gin[tid] = atomicAdd(&g_esum[tid - 64], 0.f) / (float)E;
        else if (tid < 144) gin[tid] = gfp[tid - 128];
        __syncthreads();
        if (tid < 128) {
            float sacc = bg1[tid];
            for (int k = 0; k < 144; k++) sacc += gin[k] * Wg1[(size_t)k * 128 + tid];
            ghid[tid] = fmaxf(sacc, 0.f);
        }
        __syncthreads();
        if (tid < 16) {
            float sacc = bg2[tid];
            for (int k = 0; k < 128; k++) sacc += ghid[k] * Wg2[(size_t)k * 16 + tid];
            gout[tid] = sacc;
        }
    }
}

// ---------------- launch ----------------
extern "C" void kernel_launch(void* const* d_in, const int* in_sizes, int n_in,
                              void* d_out, int out_size)
{
    const float* x   = (const float*)d_in[0];
    const int*   ei  = (const int*)d_in[1];
    const float* ea  = (const float*)d_in[2];
    const float* g   = (const float*)d_in[3];
    const float* We1 = (const float*)d_in[4];
    const float* be1 = (const float*)d_in[5];
    const float* We2 = (const float*)d_in[6];
    const float* be2 = (const float*)d_in[7];
    const float* Wn1 = (const float*)d_in[8];
    const float* bn1 = (const float*)d_in[9];
    const float* Wn2 = (const float*)d_in[10];
    const float* bn2 = (const float*)d_in[11];
    const float* Wg1 = (const float*)d_in[12];
    const float* bg1 = (const float*)d_in[13];
    const float* Wg2 = (const float*)d_in[14];
    const float* bg2 = (const float*)d_in[15];

    int N = in_sizes[0] / 64;
    int E = in_sizes[1] / 2;
    float* eout = (float*)d_out;
    float* nout = eout + (size_t)E * 64;
    float* gout = nout + (size_t)N * 64;

    cudaFuncSetAttribute(edge_tc, cudaFuncAttributeMaxDynamicSharedMemorySize, E_SMEM);
    cudaFuncSetAttribute(node_tc, cudaFuncAttributeMaxDynamicSharedMemorySize, N_SMEM);

    setup_kernel<<<(N * 16 + 255) / 256, 256>>>(N, x, g, We1, We2, Wn1, Wn2);

    int etiles = (E + 63) / 64;
    int ntl    = (N + 63) / 64;
    edge_tc<<<148, 512, E_SMEM>>>(ei, ea, be1, be2, eout, E, N, etiles);
    node_tc<<<148, 512, N_SMEM>>>(g, bn1, bn2, nout, N, ntl, E,
                                  Wg1, bg1, Wg2, bg2, gout);
}